// round 1
// baseline (speedup 1.0000x reference)
#include <cuda_runtime.h>

#define NCTAS          64
#define NTHREADS       256
#define ROWS_PER_CTA   16
#define DIM            1024
#define NGATES         8
#define MAX_TERMS      30

// Persistent scratch (device globals — no allocation allowed).
__device__ float    g_bufr[2][DIM];
__device__ float    g_bufi[2][DIM];
__device__ unsigned g_count;   // zero-initialized at module load
__device__ unsigned g_phase;   // monotonic across launches/replays — graph-safe

__device__ __forceinline__ void grid_barrier() {
    __threadfence();          // every thread: make my global writes visible at L2
    __syncthreads();
    if (threadIdx.x == 0) {
        unsigned my = *(volatile unsigned*)&g_phase;   // read BEFORE arriving
        unsigned arr = atomicAdd(&g_count, 1u);
        if (arr == NCTAS - 1) {
            atomicExch(&g_count, 0u);   // reset at L2 before release
            __threadfence();
            atomicAdd(&g_phase, 1u);    // release
        } else {
            while (*(volatile unsigned*)&g_phase == my) __nanosleep(64);
        }
        __threadfence();
    }
    __syncthreads();
}

__global__ void __launch_bounds__(NTHREADS, 1)
qnn_expm_kernel(const float* __restrict__ feature,
                const float* __restrict__ theta,
                const float* __restrict__ gens,
                float* __restrict__ out)
{
    __shared__ float svr[DIM];
    __shared__ float svi[DIM];
    __shared__ float sred[8];

    const int tid  = threadIdx.x;
    const int cta  = blockIdx.x;
    const int warp = tid >> 5;
    const int lane = tid & 31;

    // ---------- init: L2 norm of feature (computed redundantly per CTA) ----------
    float ss = 0.f;
    for (int i = tid; i < DIM; i += NTHREADS) { float f = feature[i]; ss += f * f; }
    #pragma unroll
    for (int o = 16; o; o >>= 1) ss += __shfl_xor_sync(~0u, ss, o);
    if (lane == 0) sred[warp] = ss;
    __syncthreads();
    if (warp == 0) {
        float v = (lane < 8) ? sred[lane] : 0.f;
        #pragma unroll
        for (int o = 4; o; o >>= 1) v += __shfl_xor_sync(~0u, v, o);
        if (lane == 0) sred[0] = v;
    }
    __syncthreads();
    const float inv_norm = rsqrtf(sred[0]);

    const int row0 = cta * ROWS_PER_CTA;
    // write initial psi (complex, im = 0) into buffer 0 — own rows only
    if (tid < ROWS_PER_CTA) {
        int r = row0 + tid;
        __stcg(&g_bufr[0][r], feature[r] * inv_norm);
        __stcg(&g_bufi[0][r], 0.f);
    }
    grid_barrier();

    // each warp owns 2 consecutive rows
    const int r_a = row0 + warp * 2;
    const int r_b = r_a + 1;

    float acc_re_a = 0.f, acc_im_a = 0.f, acc_re_b = 0.f, acc_im_b = 0.f; // lane 0

    int cur = 0;
    for (int g = 0; g < NGATES; g++) {
        const float t = theta[g];

        // adaptive term count: z bounds |t| * lambda_max (Wigner edge ~1.414, margin 1.5)
        const float z = 1.5f * fabsf(t) + 0.05f;
        int nterms;
        {
            float term = 1.f;
            int n = 0;
            while (n < MAX_TERMS) {
                n++;
                term *= z / (float)n;
                if (term < 1e-8f) break;
            }
            nterms = n;   // identical on every CTA (same fp ops) -> barrier-count safe
        }

        const float* G = gens + (size_t)g * DIM * DIM;

        if (lane == 0) {   // acc = w0 (own rows)
            acc_re_a = __ldcg(&g_bufr[cur][r_a]); acc_im_a = __ldcg(&g_bufi[cur][r_a]);
            acc_re_b = __ldcg(&g_bufr[cur][r_b]); acc_im_b = __ldcg(&g_bufi[cur][r_b]);
        }

        int src = cur;
        for (int n = 1; n <= nterms; n++) {
            // stage w_n into shared (SoA, conflict-free float4 reads later)
            for (int i = tid; i < DIM; i += NTHREADS) {
                svr[i] = __ldcg(&g_bufr[src][i]);
                svi[i] = __ldcg(&g_bufi[src][i]);
            }
            __syncthreads();

            float dre_a = 0.f, dim_a = 0.f, dre_b = 0.f, dim_b = 0.f;
            const float4* rowA = (const float4*)(G + (size_t)r_a * DIM);
            const float4* rowB = (const float4*)(G + (size_t)r_b * DIM);
            const float4* vr = (const float4*)svr;
            const float4* vi = (const float4*)svi;
            #pragma unroll
            for (int i = 0; i < 8; i++) {
                int idx = lane + 32 * i;
                float4 va = vr[idx];
                float4 vb = vi[idx];
                float4 ga = __ldg(&rowA[idx]);
                float4 gb = __ldg(&rowB[idx]);
                dre_a += ga.x*va.x + ga.y*va.y + ga.z*va.z + ga.w*va.w;
                dim_a += ga.x*vb.x + ga.y*vb.y + ga.z*vb.z + ga.w*vb.w;
                dre_b += gb.x*va.x + gb.y*va.y + gb.z*va.z + gb.w*va.w;
                dim_b += gb.x*vb.x + gb.y*vb.y + gb.z*vb.z + gb.w*vb.w;
            }
            #pragma unroll
            for (int o = 16; o; o >>= 1) {
                dre_a += __shfl_xor_sync(~0u, dre_a, o);
                dim_a += __shfl_xor_sync(~0u, dim_a, o);
                dre_b += __shfl_xor_sync(~0u, dre_b, o);
                dim_b += __shfl_xor_sync(~0u, dim_b, o);
            }
            if (lane == 0) {
                // w_{n+1} = (-i * t/n) * (G w_n):  (-i)(a+bi) = b - ai
                const float s = t / (float)n;
                float wre_a =  s * dim_a, wim_a = -s * dre_a;
                float wre_b =  s * dim_b, wim_b = -s * dre_b;
                acc_re_a += wre_a; acc_im_a += wim_a;
                acc_re_b += wre_b; acc_im_b += wim_b;
                __stcg(&g_bufr[src ^ 1][r_a], wre_a);
                __stcg(&g_bufi[src ^ 1][r_a], wim_a);
                __stcg(&g_bufr[src ^ 1][r_b], wre_b);
                __stcg(&g_bufi[src ^ 1][r_b], wim_b);
            }
            grid_barrier();
            src ^= 1;
        }

        // publish new psi = acc into buf[src]
        if (lane == 0) {
            __stcg(&g_bufr[src][r_a], acc_re_a);
            __stcg(&g_bufi[src][r_a], acc_im_a);
            __stcg(&g_bufr[src][r_b], acc_re_b);
            __stcg(&g_bufi[src][r_b], acc_im_b);
        }
        grid_barrier();
        cur = src;
    }

    // Born-rule probabilities from register-resident final psi (own rows)
    if (lane == 0) {
        out[r_a] = acc_re_a * acc_re_a + acc_im_a * acc_im_a;
        out[r_b] = acc_re_b * acc_re_b + acc_im_b * acc_im_b;
    }
}

extern "C" void kernel_launch(void* const* d_in, const int* in_sizes, int n_in,
                              void* d_out, int out_size) {
    // Identify inputs robustly by element count:
    //   feature: 1024, theta: 8, gens: 8*1024*1024
    const float* feature = nullptr;
    const float* theta   = nullptr;
    const float* gens    = nullptr;
    for (int i = 0; i < n_in; i++) {
        if (in_sizes[i] == DIM)                 feature = (const float*)d_in[i];
        else if (in_sizes[i] == NGATES)         theta   = (const float*)d_in[i];
        else if (in_sizes[i] == NGATES*DIM*DIM) gens    = (const float*)d_in[i];
    }
    qnn_expm_kernel<<<NCTAS, NTHREADS>>>(feature, theta, gens, (float*)d_out);
}